// round 5
// baseline (speedup 1.0000x reference)
#include <cuda_runtime.h>
#include <cstdint>
#include <cstddef>

#define BB 2
#define NN 10000
#define MM 320000
#define DD 256
#define HH 8

#define ROWS (BB*NN)   // 20000 rows per projection
#define BM 128
#define BN 128
#define BK 16

// Scratch (allocation-free rule: device globals)
__device__ float g_q[(size_t)BB*NN*DD];
__device__ float g_k[(size_t)BB*NN*DD];
__device__ float g_seg[(size_t)BB*NN*HH];
__device__ int   g_is64;

// ---------------------------------------------------------------------------
// mask dtype detection: values are in [0, N) so int64 high words are all zero.
// If the buffer is int32, "high words" are independent uniform indices in
// [0,10000) — P(64 consecutive all zero) ~ 1e-256.
// ---------------------------------------------------------------------------
__global__ void detect_kernel(const unsigned* __restrict__ w) {
    if (threadIdx.x == 0) {
        int is64 = 1;
        #pragma unroll 1
        for (int t = 0; t < 64; ++t) {
            if (w[2*t + 1] != 0u) { is64 = 0; break; }
        }
        g_is64 = is64;
    }
}

__device__ __forceinline__ int mask_at(const void* m, int row, int e, int is64) {
    if (is64) return (int)((const long long*)m)[(size_t)row*MM + e];
    return ((const int*)m)[row*MM + e];
}

__global__ void zero_seg_kernel() {
    int i = blockIdx.x * blockDim.x + threadIdx.x;
    if (i < BB*NN*HH) g_seg[i] = 0.0f;
}

// ---------------------------------------------------------------------------
// TF32 tensor-core GEMM: Y[20000,256] = X[20000,256] @ W[256,256]
// z=0: q projection, z=1: k projection
// ---------------------------------------------------------------------------
__device__ __forceinline__ unsigned f2tf32(float f) {
    unsigned u;
    asm("cvt.rna.tf32.f32 %0, %1;" : "=r"(u) : "f"(f));
    return u;
}

__global__ __launch_bounds__(256) void gemm_kernel(
    const float* __restrict__ x_q, const float* __restrict__ x_k,
    const float* __restrict__ w_q, const float* __restrict__ w_k)
{
    __shared__ unsigned As[BM][BK + 4];
    __shared__ unsigned Bs[BN][BK + 4];   // B stored transposed: Bs[n][k]

    const float* X = blockIdx.z ? x_k : x_q;
    const float* W = blockIdx.z ? w_k : w_q;
    float*       Y = blockIdx.z ? g_k  : g_q;

    const int m0   = blockIdx.x * BM;
    const int n0   = blockIdx.y * BN;
    const int tid  = threadIdx.x;
    const int lane = tid & 31;
    const int warp = tid >> 5;
    const int rB   = (warp & 3) * 32;   // warp row base within block tile
    const int nB   = (warp >> 2) * 64;  // warp col base within block tile

    float c[2][8][4];
    #pragma unroll
    for (int mt = 0; mt < 2; ++mt)
        #pragma unroll
        for (int nt = 0; nt < 8; ++nt)
            #pragma unroll
            for (int r = 0; r < 4; ++r) c[mt][nt][r] = 0.0f;

    for (int kt = 0; kt < DD; kt += BK) {
        // Load A tile 128x16 (2048 floats, 2 float4 per thread)
        #pragma unroll
        for (int l = 0; l < 2; ++l) {
            int idx = tid + l * 256;          // 0..511
            int row = idx >> 2;
            int col = (idx & 3) * 4;
            int gr  = m0 + row;
            if (gr >= ROWS) gr = ROWS - 1;    // clamp (stores are guarded)
            float4 v = *(const float4*)&X[(size_t)gr * DD + kt + col];
            As[row][col + 0] = f2tf32(v.x);
            As[row][col + 1] = f2tf32(v.y);
            As[row][col + 2] = f2tf32(v.z);
            As[row][col + 3] = f2tf32(v.w);
        }
        // Load B tile 16x128, store transposed
        #pragma unroll
        for (int l = 0; l < 2; ++l) {
            int idx = tid + l * 256;
            int k   = idx >> 5;               // 0..15
            int col = (idx & 31) * 4;         // 0..124
            float4 v = *(const float4*)&W[(size_t)(kt + k) * DD + n0 + col];
            Bs[col + 0][k] = f2tf32(v.x);
            Bs[col + 1][k] = f2tf32(v.y);
            Bs[col + 2][k] = f2tf32(v.z);
            Bs[col + 3][k] = f2tf32(v.w);
        }
        __syncthreads();

        #pragma unroll
        for (int ks = 0; ks < BK; ks += 8) {
            unsigned a[2][4], b[8][2];
            const int kc = ks + (lane & 3);
            #pragma unroll
            for (int mt = 0; mt < 2; ++mt) {
                int r = rB + mt * 16 + (lane >> 2);
                a[mt][0] = As[r][kc];
                a[mt][1] = As[r + 8][kc];
                a[mt][2] = As[r][kc + 4];
                a[mt][3] = As[r + 8][kc + 4];
            }
            #pragma unroll
            for (int nt = 0; nt < 8; ++nt) {
                int col = nB + nt * 8 + (lane >> 2);
                b[nt][0] = Bs[col][kc];
                b[nt][1] = Bs[col][kc + 4];
            }
            #pragma unroll
            for (int mt = 0; mt < 2; ++mt)
                #pragma unroll
                for (int nt = 0; nt < 8; ++nt)
                    asm volatile(
                        "mma.sync.aligned.m16n8k8.row.col.f32.tf32.tf32.f32 "
                        "{%0,%1,%2,%3}, {%4,%5,%6,%7}, {%8,%9}, {%0,%1,%2,%3};"
                        : "+f"(c[mt][nt][0]), "+f"(c[mt][nt][1]),
                          "+f"(c[mt][nt][2]), "+f"(c[mt][nt][3])
                        : "r"(a[mt][0]), "r"(a[mt][1]), "r"(a[mt][2]), "r"(a[mt][3]),
                          "r"(b[nt][0]), "r"(b[nt][1]));
        }
        __syncthreads();
    }

    // Epilogue
    #pragma unroll
    for (int mt = 0; mt < 2; ++mt) {
        int r0 = m0 + rB + mt * 16 + (lane >> 2);
        #pragma unroll
        for (int nt = 0; nt < 8; ++nt) {
            int cc = n0 + nB + nt * 8 + (lane & 3) * 2;
            if (r0 < ROWS) {
                Y[(size_t)r0 * DD + cc]     = c[mt][nt][0];
                Y[(size_t)r0 * DD + cc + 1] = c[mt][nt][1];
            }
            if (r0 + 8 < ROWS) {
                Y[(size_t)(r0 + 8) * DD + cc]     = c[mt][nt][2];
                Y[(size_t)(r0 + 8) * DD + cc + 1] = c[mt][nt][3];
            }
        }
    }
}

// ---------------------------------------------------------------------------
// Edge kernel: one warp per (b, edge). Gather q-row & k-row (L2 resident),
// per-head dot (32 dims = 4 lanes), e = exp(dot/16) [global-max shift is
// algebraically redundant in e/(seg+eps)], write e, scatter-add into seg.
// ---------------------------------------------------------------------------
__global__ __launch_bounds__(256) void edge_kernel(const void* __restrict__ mask,
                                                   float* __restrict__ out)
{
    const int is64 = g_is64;
    long long wgl = (long long)blockIdx.x * 8 + (threadIdx.x >> 5);
    if (wgl >= (long long)BB * MM) return;
    const int b    = (int)(wgl / MM);
    const int e    = (int)(wgl % MM);
    const int lane = threadIdx.x & 31;

    const int i = mask_at(mask, 0, e, is64);
    const int j = mask_at(mask, 1, e, is64);

    const float4* qr = (const float4*)(g_q + ((size_t)b * NN + i) * DD);
    const float4* kr = (const float4*)(g_k + ((size_t)b * NN + j) * DD);
    float4 q0 = qr[lane * 2], q1 = qr[lane * 2 + 1];
    float4 k0 = kr[lane * 2], k1 = kr[lane * 2 + 1];

    float s = q0.x * k0.x + q0.y * k0.y + q0.z * k0.z + q0.w * k0.w
            + q1.x * k1.x + q1.y * k1.y + q1.z * k1.z + q1.w * k1.w;
    s += __shfl_xor_sync(0xffffffffu, s, 1);
    s += __shfl_xor_sync(0xffffffffu, s, 2);

    if ((lane & 3) == 0) {
        int h = lane >> 2;
        float v = expf(s * 0.0625f);   // /sqrt(256)
        out[((size_t)b * MM + e) * HH + h] = v;
        atomicAdd(&g_seg[((size_t)b * NN + i) * HH + h], v);
    }
}

// ---------------------------------------------------------------------------
// Normalize: out[b,e,h] /= (seg[b, mask0[e], h] + 1e-16)
// ---------------------------------------------------------------------------
__global__ __launch_bounds__(256) void norm_kernel(const void* __restrict__ mask,
                                                   float* __restrict__ out)
{
    long long g = (long long)blockIdx.x * blockDim.x + threadIdx.x;
    if (g >= (long long)BB * MM * HH) return;
    const int is64 = g_is64;
    int h = (int)(g & 7);
    long long rest = g >> 3;
    int e = (int)(rest % MM);
    int b = (int)(rest / MM);
    int i = mask_at(mask, 0, e, is64);
    out[g] = out[g] / (g_seg[((size_t)b * NN + i) * HH + h] + 1e-16f);
}

// ---------------------------------------------------------------------------
extern "C" void kernel_launch(void* const* d_in, const int* in_sizes, int n_in,
                              void* d_out, int out_size)
{
    const float* x_q  = (const float*)d_in[0];
    const float* x_k  = (const float*)d_in[1];
    const void*  mask = d_in[2];
    const float* w_q  = (const float*)d_in[3];
    const float* w_k  = (const float*)d_in[4];
    float* out = (float*)d_out;

    detect_kernel<<<1, 32>>>((const unsigned*)mask);
    zero_seg_kernel<<<(BB*NN*HH + 255) / 256, 256>>>();

    dim3 gg((ROWS + BM - 1) / BM, DD / BN, 2);
    gemm_kernel<<<gg, 256>>>(x_q, x_k, w_q, w_k);

    long long warps = (long long)BB * MM;                 // 640000
    edge_kernel<<<(unsigned)((warps + 7) / 8), 256>>>(mask, out);

    long long total = (long long)BB * MM * HH;            // 5.12M
    norm_kernel<<<(unsigned)((total + 255) / 256), 256>>>(mask, out);
}

// round 6
// speedup vs baseline: 1.5495x; 1.5495x over previous
#include <cuda_runtime.h>
#include <cuda_bf16.h>
#include <cstdint>
#include <cstddef>

#define BB 2
#define NN 10000
#define MM 320000
#define DD 256
#define HH 8

#define ROWS (BB*NN)   // 20000 rows per projection
#define BM 128
#define BN 128
#define BK 16
#define PAD 20         // smem row stride in words (conflict-free, see notes)
#define NKT (DD/BK)    // 16 k-tiles

// Scratch (allocation-free rule: device globals)
__device__ __nv_bfloat16 g_qh[(size_t)BB*NN*DD];
__device__ __nv_bfloat16 g_kh[(size_t)BB*NN*DD];
__device__ float g_seg[(size_t)BB*NN*HH];
__device__ float g_inv[(size_t)BB*NN*HH];
__device__ int   g_is64;

// ---------------------------------------------------------------------------
// mask dtype detection: values in [0, N) so int64 high words are all zero.
// int32 false-positive probability over 64 words ~ 1e-256.
// ---------------------------------------------------------------------------
__global__ void detect_kernel(const unsigned* __restrict__ w) {
    if (threadIdx.x == 0) {
        int is64 = 1;
        #pragma unroll 1
        for (int t = 0; t < 64; ++t) {
            if (w[2*t + 1] != 0u) { is64 = 0; break; }
        }
        g_is64 = is64;
    }
}

__device__ __forceinline__ int mask_at(const void* m, int row, int e, int is64) {
    if (is64) return (int)((const long long*)m)[(size_t)row*MM + e];
    return ((const int*)m)[row*MM + e];
}

__global__ void zero_seg_kernel() {
    int i = blockIdx.x * blockDim.x + threadIdx.x;
    if (i < BB*NN*HH) g_seg[i] = 0.0f;
}

// ---------------------------------------------------------------------------
// TF32 tensor-core GEMM, software-pipelined double buffer.
// Y[20000,256](bf16) = X[20000,256] @ W[256,256];  z=0: q, z=1: k
// ---------------------------------------------------------------------------
__device__ __forceinline__ unsigned f2tf32(float f) {
    unsigned u;
    asm("cvt.rna.tf32.f32 %0, %1;" : "=r"(u) : "f"(f));
    return u;
}

__global__ __launch_bounds__(256, 2) void gemm_kernel(
    const float* __restrict__ x_q, const float* __restrict__ x_k,
    const float* __restrict__ w_q, const float* __restrict__ w_k)
{
    // A: [m][k] stride 20 -> consumer banks (20g+t) all-distinct, conflict-free
    // B: [n][k] stride 20 -> same consumer pattern; producer stores one
    //    contiguous k-run per thread (STS.128, bank groups 5n mod 8 distinct)
    __shared__ unsigned As[2][BM * PAD];
    __shared__ unsigned Bs[2][BN * PAD];

    const float* X = blockIdx.z ? x_k : x_q;
    const float* W = blockIdx.z ? w_k : w_q;
    __nv_bfloat16* Y = blockIdx.z ? g_kh : g_qh;

    const int m0   = blockIdx.x * BM;
    const int n0   = blockIdx.y * BN;
    const int tid  = threadIdx.x;
    const int lane = tid & 31;
    const int warp = tid >> 5;
    const int rB   = (warp & 3) * 32;   // warp row base in tile
    const int nB   = (warp >> 2) * 64;  // warp col base in tile

    // producer indices
    const int ar  = tid >> 2;            // A rows ar, ar+64
    const int ac  = (tid & 3) * 4;       // A col chunk
    const int bn  = tid & 127;           // B n index
    const int bk0 = (tid >> 7) * 8;      // B k base (0 or 8)

    int gr0 = m0 + ar;      if (gr0 >= ROWS) gr0 = ROWS - 1;
    int gr1 = m0 + ar + 64; if (gr1 >= ROWS) gr1 = ROWS - 1;
    const float* xp0 = X + (size_t)gr0 * DD + ac;
    const float* xp1 = X + (size_t)gr1 * DD + ac;
    const float* wp  = W + (size_t)bk0 * DD + n0 + bn;

    float c[2][8][4];
    #pragma unroll
    for (int mt = 0; mt < 2; ++mt)
        #pragma unroll
        for (int nt = 0; nt < 8; ++nt)
            #pragma unroll
            for (int r = 0; r < 4; ++r) c[mt][nt][r] = 0.0f;

    float4 a0, a1;
    float  br[8];

    // prologue: load kt=0
    a0 = *(const float4*)xp0;
    a1 = *(const float4*)xp1;
    #pragma unroll
    for (int s = 0; s < 8; ++s) br[s] = wp[(size_t)s * DD];

    {   // store tile 0 into buf 0
        unsigned* A = As[0]; unsigned* Bp = Bs[0];
        A[ar*PAD + ac+0] = f2tf32(a0.x); A[ar*PAD + ac+1] = f2tf32(a0.y);
        A[ar*PAD + ac+2] = f2tf32(a0.z); A[ar*PAD + ac+3] = f2tf32(a0.w);
        A[(ar+64)*PAD + ac+0] = f2tf32(a1.x); A[(ar+64)*PAD + ac+1] = f2tf32(a1.y);
        A[(ar+64)*PAD + ac+2] = f2tf32(a1.z); A[(ar+64)*PAD + ac+3] = f2tf32(a1.w);
        #pragma unroll
        for (int s = 0; s < 8; ++s) Bp[bn*PAD + bk0 + s] = f2tf32(br[s]);
    }
    __syncthreads();

    #pragma unroll 1
    for (int kt = 0; kt < NKT; ++kt) {
        // issue next tile's global loads early (hidden behind compute)
        if (kt + 1 < NKT) {
            int ko = (kt + 1) * BK;
            a0 = *(const float4*)(xp0 + ko);
            a1 = *(const float4*)(xp1 + ko);
            #pragma unroll
            for (int s = 0; s < 8; ++s) br[s] = wp[(size_t)(ko + s) * DD];
        }

        // compute from buf kt&1
        {
            const unsigned* A  = As[kt & 1];
            const unsigned* Bp = Bs[kt & 1];
            #pragma unroll
            for (int ks = 0; ks < BK; ks += 8) {
                unsigned a[2][4], b[8][2];
                const int kc = ks + (lane & 3);
                #pragma unroll
                for (int mt = 0; mt < 2; ++mt) {
                    int r = rB + mt * 16 + (lane >> 2);
                    a[mt][0] = A[r*PAD + kc];
                    a[mt][1] = A[(r+8)*PAD + kc];
                    a[mt][2] = A[r*PAD + kc + 4];
                    a[mt][3] = A[(r+8)*PAD + kc + 4];
                }
                #pragma unroll
                for (int nt = 0; nt < 8; ++nt) {
                    int col = nB + nt * 8 + (lane >> 2);
                    b[nt][0] = Bp[col*PAD + kc];
                    b[nt][1] = Bp[col*PAD + kc + 4];
                }
                #pragma unroll
                for (int mt = 0; mt < 2; ++mt)
                    #pragma unroll
                    for (int nt = 0; nt < 8; ++nt)
                        asm volatile(
                            "mma.sync.aligned.m16n8k8.row.col.f32.tf32.tf32.f32 "
                            "{%0,%1,%2,%3}, {%4,%5,%6,%7}, {%8,%9}, {%0,%1,%2,%3};"
                            : "+f"(c[mt][nt][0]), "+f"(c[mt][nt][1]),
                              "+f"(c[mt][nt][2]), "+f"(c[mt][nt][3])
                            : "r"(a[mt][0]), "r"(a[mt][1]), "r"(a[mt][2]), "r"(a[mt][3]),
                              "r"(b[nt][0]), "r"(b[nt][1]));
            }
        }

        // store next tile into the other buffer (prev readers done by last sync)
        if (kt + 1 < NKT) {
            unsigned* A = As[(kt+1) & 1]; unsigned* Bp = Bs[(kt+1) & 1];
            A[ar*PAD + ac+0] = f2tf32(a0.x); A[ar*PAD + ac+1] = f2tf32(a0.y);
            A[ar*PAD + ac+2] = f2tf32(a0.z); A[ar*PAD + ac+3] = f2tf32(a0.w);
            A[(ar+64)*PAD + ac+0] = f2tf32(a1.x); A[(ar+64)*PAD + ac+1] = f2tf32(a1.y);
            A[(ar+64)*PAD + ac+2] = f2tf32(a1.z); A[(ar+64)*PAD + ac+3] = f2tf32(a1.w);
            #pragma unroll
            for (int s = 0; s < 8; ++s) Bp[bn*PAD + bk0 + s] = f2tf32(br[s]);
        }
        __syncthreads();
    }

    // Epilogue -> bf16
    #pragma unroll
    for (int mt = 0; mt < 2; ++mt) {
        int r0 = m0 + rB + mt * 16 + (lane >> 2);
        #pragma unroll
        for (int nt = 0; nt < 8; ++nt) {
            int cc = n0 + nB + nt * 8 + (lane & 3) * 2;
            if (r0 < ROWS) {
                __nv_bfloat162 h = __float22bfloat162_rn(
                    make_float2(c[mt][nt][0], c[mt][nt][1]));
                *(__nv_bfloat162*)&Y[(size_t)r0 * DD + cc] = h;
            }
            if (r0 + 8 < ROWS) {
                __nv_bfloat162 h = __float22bfloat162_rn(
                    make_float2(c[mt][nt][2], c[mt][nt][3]));
                *(__nv_bfloat162*)&Y[(size_t)(r0 + 8) * DD + cc] = h;
            }
        }
    }
}

// ---------------------------------------------------------------------------
// Edge kernel: one warp per (b, edge). bf16 gather (512B/row, one LDG.128
// warp-wide per row), per-head dot over 32 dims (4 lanes x 8 dims), shfl
// reduce, exp (global-max shift is algebraically redundant in e/(seg+eps)),
// coalesced 32B out store from lanes 0..7, scatter-add into seg.
// ---------------------------------------------------------------------------
__global__ __launch_bounds__(256) void edge_kernel(const void* __restrict__ mask,
                                                   float* __restrict__ out)
{
    const int is64 = g_is64;
    long long wgl = (long long)blockIdx.x * 8 + (threadIdx.x >> 5);
    if (wgl >= (long long)BB * MM) return;
    const int b    = (int)(wgl / MM);
    const int e    = (int)(wgl % MM);
    const int lane = threadIdx.x & 31;

    const int i = mask_at(mask, 0, e, is64);
    const int j = mask_at(mask, 1, e, is64);

    const uint4* qr = (const uint4*)(g_qh + ((size_t)b * NN + i) * DD);
    const uint4* kr = (const uint4*)(g_kh + ((size_t)b * NN + j) * DD);
    uint4 qv = qr[lane];    // dims lane*8 .. lane*8+7, head = lane>>2
    uint4 kv = kr[lane];

    const __nv_bfloat162* qp = (const __nv_bfloat162*)&qv;
    const __nv_bfloat162* kp = (const __nv_bfloat162*)&kv;
    float s = 0.0f;
    #pragma unroll
    for (int p = 0; p < 4; ++p) {
        float2 fa = __bfloat1622float2(qp[p]);
        float2 fb = __bfloat1622float2(kp[p]);
        s += fa.x * fb.x + fa.y * fb.y;
    }
    s += __shfl_xor_sync(0xffffffffu, s, 1);
    s += __shfl_xor_sync(0xffffffffu, s, 2);   // quad 4h..4h+3 all hold head h sum

    float sh = __shfl_sync(0xffffffffu, s, (lane & 7) * 4);  // lane<8 gets head `lane`
    if (lane < 8) {
        float v = __expf(sh * 0.0625f);   // /sqrt(256)
        out[((size_t)b * MM + e) * HH + lane] = v;
        atomicAdd(&g_seg[((size_t)b * NN + i) * HH + lane], v);
    }
}

// ---------------------------------------------------------------------------
// inv: one rcp per (b, node, h) instead of 5.12M in the norm pass
// ---------------------------------------------------------------------------
__global__ void inv_kernel() {
    int idx = blockIdx.x * blockDim.x + threadIdx.x;
    if (idx < BB*NN*HH) g_inv[idx] = 1.0f / (g_seg[idx] + 1e-16f);
}

// ---------------------------------------------------------------------------
// Normalize: thread per (b, edge); float4 x2 multiply by gathered inv row.
// ---------------------------------------------------------------------------
__global__ __launch_bounds__(256) void norm_kernel(const void* __restrict__ mask,
                                                   float* __restrict__ out)
{
    long long t = (long long)blockIdx.x * blockDim.x + threadIdx.x;
    if (t >= (long long)BB * MM) return;
    const int is64 = g_is64;
    const int b = (int)(t / MM);
    const int e = (int)(t % MM);
    const int i = mask_at(mask, 0, e, is64);

    const float4* iv = (const float4*)(g_inv + ((size_t)b * NN + i) * HH);
    float4 s0 = iv[0], s1 = iv[1];
    float4* op = (float4*)(out + ((size_t)b * MM + e) * HH);
    float4 o0 = op[0], o1 = op[1];
    o0.x *= s0.x; o0.y *= s0.y; o0.z *= s0.z; o0.w *= s0.w;
    o1.x *= s1.x; o1.y *= s1.y; o1.z *= s1.z; o1.w *= s1.w;
    op[0] = o0; op[1] = o1;
}

// ---------------------------------------------------------------------------
extern "C" void kernel_launch(void* const* d_in, const int* in_sizes, int n_in,
                              void* d_out, int out_size)
{
    const float* x_q  = (const float*)d_in[0];
    const float* x_k  = (const float*)d_in[1];
    const void*  mask = d_in[2];
    const float* w_q  = (const float*)d_in[3];
    const float* w_k  = (const float*)d_in[4];
    float* out = (float*)d_out;

    detect_kernel<<<1, 32>>>((const unsigned*)mask);
    zero_seg_kernel<<<(BB*NN*HH + 255) / 256, 256>>>();

    dim3 gg((ROWS + BM - 1) / BM, DD / BN, 2);
    gemm_kernel<<<gg, 256>>>(x_q, x_k, w_q, w_k);

    long long warps = (long long)BB * MM;                 // 640000
    edge_kernel<<<(unsigned)((warps + 7) / 8), 256>>>(mask, out);

    inv_kernel<<<(BB*NN*HH + 255) / 256, 256>>>();

    long long edges = (long long)BB * MM;                 // 640000
    norm_kernel<<<(unsigned)((edges + 255) / 256), 256>>>(mask, out);
}

// round 9
// speedup vs baseline: 1.6423x; 1.0599x over previous
#include <cuda_runtime.h>
#include <cuda_bf16.h>
#include <cstdint>
#include <cstddef>

#define BB 2
#define NN 10000
#define MM 320000
#define DD 256
#define HH 8

#define ROWS (BB*NN)   // 20000 rows per projection
#define BM 128
#define BN 128
#define BK 16
#define PAD 20         // smem row stride in words (conflict-free)
#define NKT (DD/BK)    // 16 k-tiles

// Scratch (allocation-free rule: device globals)
__device__ __nv_bfloat16 g_qh[(size_t)BB*NN*DD];
__device__ __nv_bfloat16 g_kh[(size_t)BB*NN*DD];
__device__ float g_seg[(size_t)BB*NN*HH];
__device__ float g_inv[(size_t)BB*NN*HH];
__device__ int   g_is64;

// ---------------------------------------------------------------------------
// mask dtype detection: values in [0, N) so int64 high words are all zero.
// int32 false-positive probability over 64 words ~ 1e-256.
// ---------------------------------------------------------------------------
__global__ void detect_kernel(const unsigned* __restrict__ w) {
    if (threadIdx.x == 0) {
        int is64 = 1;
        #pragma unroll 1
        for (int t = 0; t < 64; ++t) {
            if (w[2*t + 1] != 0u) { is64 = 0; break; }
        }
        g_is64 = is64;
    }
}

// row is a compile-time 0/1; all offsets fit 32-bit.
__device__ __forceinline__ int mask_at(const void* m, int row, int e, int is64) {
    if (is64) return (int)((const long long*)m)[(unsigned)(row*MM + e)];
    return ((const int*)m)[(unsigned)(row*MM + e)];
}

__global__ void zero_seg_kernel() {
    int i = blockIdx.x * blockDim.x + threadIdx.x;
    if (i < BB*NN*HH) g_seg[i] = 0.0f;
}

// ---------------------------------------------------------------------------
// TF32 tensor-core GEMM, software-pipelined double buffer.
// Y[20000,256](bf16) = X[20000,256] @ W[256,256];  z=0: q, z=1: k
// ---------------------------------------------------------------------------
__device__ __forceinline__ unsigned f2tf32(float f) {
    unsigned u;
    asm("cvt.rna.tf32.f32 %0, %1;" : "=r"(u) : "f"(f));
    return u;
}

__global__ __launch_bounds__(256, 2) void gemm_kernel(
    const float* __restrict__ x_q, const float* __restrict__ x_k,
    const float* __restrict__ w_q, const float* __restrict__ w_k)
{
    __shared__ unsigned As[2][BM * PAD];
    __shared__ unsigned Bs[2][BN * PAD];

    const float* X = blockIdx.z ? x_k : x_q;
    const float* W = blockIdx.z ? w_k : w_q;
    __nv_bfloat16* Y = blockIdx.z ? g_kh : g_qh;

    const int m0   = blockIdx.x * BM;
    const int n0   = blockIdx.y * BN;
    const int tid  = threadIdx.x;
    const int lane = tid & 31;
    const int warp = tid >> 5;
    const int rB   = (warp & 3) * 32;   // warp row base in tile
    const int nB   = (warp >> 2) * 64;  // warp col base in tile

    // producer indices
    const int ar  = tid >> 2;            // A rows ar, ar+64
    const int ac  = (tid & 3) * 4;       // A col chunk
    const int bn  = tid & 127;           // B n index
    const int bk0 = (tid >> 7) * 8;      // B k base (0 or 8)

    int gr0 = m0 + ar;      if (gr0 >= ROWS) gr0 = ROWS - 1;
    int gr1 = m0 + ar + 64; if (gr1 >= ROWS) gr1 = ROWS - 1;
    const float* xp0 = X + (size_t)gr0 * DD + ac;
    const float* xp1 = X + (size_t)gr1 * DD + ac;
    const float* wp  = W + (size_t)bk0 * DD + n0 + bn;

    float c[2][8][4];
    #pragma unroll
    for (int mt = 0; mt < 2; ++mt)
        #pragma unroll
        for (int nt = 0; nt < 8; ++nt)
            #pragma unroll
            for (int r = 0; r < 4; ++r) c[mt][nt][r] = 0.0f;

    float4 a0, a1;
    float  br[8];

    // prologue: load kt=0
    a0 = *(const float4*)xp0;
    a1 = *(const float4*)xp1;
    #pragma unroll
    for (int s = 0; s < 8; ++s) br[s] = wp[(size_t)s * DD];

    {   // store tile 0 into buf 0
        unsigned* A = As[0]; unsigned* Bp = Bs[0];
        A[ar*PAD + ac+0] = f2tf32(a0.x); A[ar*PAD + ac+1] = f2tf32(a0.y);
        A[ar*PAD + ac+2] = f2tf32(a0.z); A[ar*PAD + ac+3] = f2tf32(a0.w);
        A[(ar+64)*PAD + ac+0] = f2tf32(a1.x); A[(ar+64)*PAD + ac+1] = f2tf32(a1.y);
        A[(ar+64)*PAD + ac+2] = f2tf32(a1.z); A[(ar+64)*PAD + ac+3] = f2tf32(a1.w);
        #pragma unroll
        for (int s = 0; s < 8; ++s) Bp[bn*PAD + bk0 + s] = f2tf32(br[s]);
    }
    __syncthreads();

    #pragma unroll 2
    for (int kt = 0; kt < NKT; ++kt) {
        // issue next tile's global loads early (hidden behind compute)
        if (kt + 1 < NKT) {
            int ko = (kt + 1) * BK;
            a0 = *(const float4*)(xp0 + ko);
            a1 = *(const float4*)(xp1 + ko);
            #pragma unroll
            for (int s = 0; s < 8; ++s) br[s] = wp[(size_t)(ko + s) * DD];
        }

        // compute from buf kt&1
        {
            const unsigned* A  = As[kt & 1];
            const unsigned* Bp = Bs[kt & 1];
            #pragma unroll
            for (int ks = 0; ks < BK; ks += 8) {
                unsigned a[2][4], b[8][2];
                const int kc = ks + (lane & 3);
                #pragma unroll
                for (int mt = 0; mt < 2; ++mt) {
                    int r = rB + mt * 16 + (lane >> 2);
                    a[mt][0] = A[r*PAD + kc];
                    a[mt][1] = A[(r+8)*PAD + kc];
                    a[mt][2] = A[r*PAD + kc + 4];
                    a[mt][3] = A[(r+8)*PAD + kc + 4];
                }
                #pragma unroll
                for (int nt = 0; nt < 8; ++nt) {
                    int col = nB + nt * 8 + (lane >> 2);
                    b[nt][0] = Bp[col*PAD + kc];
                    b[nt][1] = Bp[col*PAD + kc + 4];
                }
                #pragma unroll
                for (int mt = 0; mt < 2; ++mt)
                    #pragma unroll
                    for (int nt = 0; nt < 8; ++nt)
                        asm volatile(
                            "mma.sync.aligned.m16n8k8.row.col.f32.tf32.tf32.f32 "
                            "{%0,%1,%2,%3}, {%4,%5,%6,%7}, {%8,%9}, {%0,%1,%2,%3};"
                            : "+f"(c[mt][nt][0]), "+f"(c[mt][nt][1]),
                              "+f"(c[mt][nt][2]), "+f"(c[mt][nt][3])
                            : "r"(a[mt][0]), "r"(a[mt][1]), "r"(a[mt][2]), "r"(a[mt][3]),
                              "r"(b[nt][0]), "r"(b[nt][1]));
            }
        }

        // store next tile into the other buffer (prev readers done by last sync)
        if (kt + 1 < NKT) {
            unsigned* A = As[(kt+1) & 1]; unsigned* Bp = Bs[(kt+1) & 1];
            A[ar*PAD + ac+0] = f2tf32(a0.x); A[ar*PAD + ac+1] = f2tf32(a0.y);
            A[ar*PAD + ac+2] = f2tf32(a0.z); A[ar*PAD + ac+3] = f2tf32(a0.w);
            A[(ar+64)*PAD + ac+0] = f2tf32(a1.x); A[(ar+64)*PAD + ac+1] = f2tf32(a1.y);
            A[(ar+64)*PAD + ac+2] = f2tf32(a1.z); A[(ar+64)*PAD + ac+3] = f2tf32(a1.w);
            #pragma unroll
            for (int s = 0; s < 8; ++s) Bp[bn*PAD + bk0 + s] = f2tf32(br[s]);
        }
        __syncthreads();
    }

    // Epilogue -> bf16
    #pragma unroll
    for (int mt = 0; mt < 2; ++mt) {
        int r0 = m0 + rB + mt * 16 + (lane >> 2);
        #pragma unroll
        for (int nt = 0; nt < 8; ++nt) {
            int cc = n0 + nB + nt * 8 + (lane & 3) * 2;
            if (r0 < ROWS) {
                __nv_bfloat162 h = __float22bfloat162_rn(
                    make_float2(c[mt][nt][0], c[mt][nt][1]));
                *(__nv_bfloat162*)&Y[(size_t)r0 * DD + cc] = h;
            }
            if (r0 + 8 < ROWS) {
                __nv_bfloat162 h = __float22bfloat162_rn(
                    make_float2(c[mt][nt][2], c[mt][nt][3]));
                *(__nv_bfloat162*)&Y[(size_t)(r0 + 8) * DD + cc] = h;
            }
        }
    }
}

// ---------------------------------------------------------------------------
// Edge kernel: one warp per edge, batch = blockIdx.y. Pure 32-bit indexing,
// exact grid (no bounds checks), no 64-bit division. bf16 gather (512B/row,
// one LDG.128 warp-wide per row), per-head dot (4 lanes x 8 dims), 2 xor
// shfls; quad leaders hold head sums -> exp/store/atomic directly.
// Global-max shift is algebraically redundant in e/(seg+eps).
// ---------------------------------------------------------------------------
__global__ __launch_bounds__(256) void edge_kernel(const void* __restrict__ mask,
                                                   float* __restrict__ out)
{
    const int is64 = g_is64;
    const int b    = blockIdx.y;
    const int e    = (int)(blockIdx.x * 8u + (threadIdx.x >> 5));
    const int lane = threadIdx.x & 31;

    const int i = mask_at(mask, 0, e, is64);
    const int j = mask_at(mask, 1, e, is64);

    const unsigned rq = (unsigned)(b * NN + i) * DD;   // <= 5.12M, 32-bit safe
    const unsigned rk = (unsigned)(b * NN + j) * DD;
    const uint4* qr = (const uint4*)(g_qh + rq);
    const uint4* kr = (const uint4*)(g_kh + rk);
    uint4 qv = qr[lane];    // dims lane*8 .. lane*8+7, head = lane>>2
    uint4 kv = kr[lane];

    const __nv_bfloat162* qp = (const __nv_bfloat162*)&qv;
    const __nv_bfloat162* kp = (const __nv_bfloat162*)&kv;
    float s = 0.0f;
    #pragma unroll
    for (int p = 0; p < 4; ++p) {
        float2 fa = __bfloat1622float2(qp[p]);
        float2 fb = __bfloat1622float2(kp[p]);
        s += fa.x * fb.x + fa.y * fb.y;
    }
    s += __shfl_xor_sync(0xffffffffu, s, 1);
    s += __shfl_xor_sync(0xffffffffu, s, 2);   // quad 4h..4h+3 hold head-h sum

    if ((lane & 3) == 0) {
        const int h = lane >> 2;
        float v = __expf(s * 0.0625f);   // /sqrt(256)
        out[(unsigned)(b * MM + e) * HH + h] = v;   // lanes 0,4..28 -> one 32B seg
        atomicAdd(&g_seg[(unsigned)(b * NN + i) * HH + h], v);
    }
}

// ---------------------------------------------------------------------------
// inv: one rcp per (b, node, h) instead of 5.12M in the norm pass
// ---------------------------------------------------------------------------
__global__ void inv_kernel() {
    int idx = blockIdx.x * blockDim.x + threadIdx.x;
    if (idx < BB*NN*HH) g_inv[idx] = 1.0f / (g_seg[idx] + 1e-16f);
}

// ---------------------------------------------------------------------------
// Normalize: thread per edge, batch = blockIdx.y; float4 x2 multiply by
// gathered inv row. Exact grid, 32-bit indexing.
// ---------------------------------------------------------------------------
__global__ __launch_bounds__(256) void norm_kernel(const void* __restrict__ mask,
                                                   float* __restrict__ out)
{
    const int is64 = g_is64;
    const int b = blockIdx.y;
    const int e = (int)(blockIdx.x * 256u + threadIdx.x);
    const int i = mask_at(mask, 0, e, is64);

    const float4* iv = (const float4*)(g_inv + (unsigned)(b * NN + i) * HH);
    float4 s0 = iv[0], s1 = iv[1];
    float4* op = (float4*)(out + (unsigned)(b * MM + e) * HH);
    float4 o0 = op[0], o1 = op[1];
    o0.x *= s0.x; o0.y *= s0.y; o0.z *= s0.z; o0.w *= s0.w;
    o1.x *= s1.x; o1.y *= s1.y; o1.z *= s1.z; o1.w *= s1.w;
    op[0] = o0; op[1] = o1;
}

// ---------------------------------------------------------------------------
extern "C" void kernel_launch(void* const* d_in, const int* in_sizes, int n_in,
                              void* d_out, int out_size)
{
    const float* x_q  = (const float*)d_in[0];
    const float* x_k  = (const float*)d_in[1];
    const void*  mask = d_in[2];
    const float* w_q  = (const float*)d_in[3];
    const float* w_k  = (const float*)d_in[4];
    float* out = (float*)d_out;

    detect_kernel<<<1, 32>>>((const unsigned*)mask);
    zero_seg_kernel<<<(BB*NN*HH + 255) / 256, 256>>>();

    dim3 gg((ROWS + BM - 1) / BM, DD / BN, 2);
    gemm_kernel<<<gg, 256>>>(x_q, x_k, w_q, w_k);

    dim3 ge(MM / 8, BB);            // 8 warps/block, exact cover
    edge_kernel<<<ge, 256>>>(mask, out);

    inv_kernel<<<(BB*NN*HH + 255) / 256, 256>>>();

    dim3 gn(MM / 256, BB);          // exact cover
    norm_kernel<<<gn, 256>>>(mask, out);
}

// round 10
// speedup vs baseline: 2.0131x; 1.2258x over previous
#include <cuda_runtime.h>
#include <cuda_bf16.h>
#include <cuda_fp16.h>
#include <cstdint>
#include <cstddef>

#define BB 2
#define NN 10000
#define MM 320000
#define DD 256
#define HH 8

#define ROWS (BB*NN)   // 20000 rows per projection
#define BM 128
#define BN 128
#define BK 16
#define KW 8           // half2 words per row (BK/2)
#define NKT (DD/BK)    // 16 k-tiles

// Scratch (allocation-free rule: device globals)
__device__ __nv_bfloat16 g_qh[(size_t)BB*NN*DD];
__device__ __nv_bfloat16 g_kh[(size_t)BB*NN*DD];
__device__ float g_seg[(size_t)BB*NN*HH];
__device__ float g_inv[(size_t)BB*NN*HH];
__device__ int   g_is64;

// ---------------------------------------------------------------------------
// mask dtype detection: values in [0, N) so int64 high words are all zero.
// ---------------------------------------------------------------------------
__global__ void detect_kernel(const unsigned* __restrict__ w) {
    if (threadIdx.x == 0) {
        int is64 = 1;
        #pragma unroll 1
        for (int t = 0; t < 64; ++t) {
            if (w[2*t + 1] != 0u) { is64 = 0; break; }
        }
        g_is64 = is64;
    }
}

__device__ __forceinline__ int mask_at(const void* m, int row, int e, int is64) {
    if (is64) return (int)((const long long*)m)[(unsigned)(row*MM + e)];
    return ((const int*)m)[(unsigned)(row*MM + e)];
}

__global__ void zero_seg_kernel() {
    int i = blockIdx.x * blockDim.x + threadIdx.x;
    if (i < BB*NN*HH) g_seg[i] = 0.0f;
}

// ---------------------------------------------------------------------------
// FP16 tensor-core GEMM (m16n8k16, f32 accum) — same 10-bit mantissa as tf32,
// 2x rate. Software-pipelined double buffer, XOR-swizzled half2 smem.
// Y[20000,256](bf16) = X[20000,256] @ W[256,256];  z=0: q, z=1: k
// ---------------------------------------------------------------------------
__device__ __forceinline__ unsigned packh2(float a, float b) {
    __half2 h = __floats2half2_rn(a, b);   // lo=a, hi=b
    return *(unsigned*)&h;
}

__global__ __launch_bounds__(256, 2) void gemm_kernel(
    const float* __restrict__ x_q, const float* __restrict__ x_k,
    const float* __restrict__ w_q, const float* __restrict__ w_k)
{
    // word address = row*KW + (w ^ (row&7)); consumer banks are a permutation
    // of 0..31 for every fragment load (see notes).
    __shared__ unsigned As[2][BM * KW];
    __shared__ unsigned Bs[2][BN * KW];

    const float* X = blockIdx.z ? x_k : x_q;
    const float* W = blockIdx.z ? w_k : w_q;
    __nv_bfloat16* Y = blockIdx.z ? g_kh : g_qh;

    const int m0   = blockIdx.x * BM;
    const int n0   = blockIdx.y * BN;
    const int tid  = threadIdx.x;
    const int lane = tid & 31;
    const int warp = tid >> 5;
    const int rB   = (warp & 3) * 32;   // warp row base in tile
    const int nB   = (warp >> 2) * 64;  // warp col base in tile

    // producer indices
    const int ar  = tid >> 2;            // A rows ar, ar+64
    const int ac  = (tid & 3) * 4;       // A col chunk (4 floats = 2 words)
    const int wa  = (tid & 3) * 2;       // A word base
    const int bn  = tid & 127;           // B n index
    const int bk0 = (tid >> 7) * 8;      // B k base (0 or 8)
    const int wb  = bk0 >> 1;            // B word base (0 or 4)

    int gr0 = m0 + ar;      if (gr0 >= ROWS) gr0 = ROWS - 1;
    int gr1 = m0 + ar + 64; if (gr1 >= ROWS) gr1 = ROWS - 1;
    const float* xp0 = X + (size_t)gr0 * DD + ac;
    const float* xp1 = X + (size_t)gr1 * DD + ac;
    const float* wp  = W + (size_t)bk0 * DD + n0 + bn;

    float c[2][8][4];
    #pragma unroll
    for (int mt = 0; mt < 2; ++mt)
        #pragma unroll
        for (int nt = 0; nt < 8; ++nt)
            #pragma unroll
            for (int r = 0; r < 4; ++r) c[mt][nt][r] = 0.0f;

    float4 a0v, a1v;
    float  br[8];

    const int sw0 = ar & 7;          // A swizzle sel rows ar / ar+64 (same &7... no)
    const int sw1 = (ar + 64) & 7;   // (ar+64)&7 == ar&7 actually; keep explicit
    const int swb = bn & 7;

    // prologue: load kt=0
    a0v = *(const float4*)xp0;
    a1v = *(const float4*)xp1;
    #pragma unroll
    for (int s = 0; s < 8; ++s) br[s] = wp[(size_t)s * DD];

    {   // store tile 0 into buf 0
        unsigned* A = As[0]; unsigned* Bp = Bs[0];
        A[ar*KW       + ((wa+0) ^ sw0)] = packh2(a0v.x, a0v.y);
        A[ar*KW       + ((wa+1) ^ sw0)] = packh2(a0v.z, a0v.w);
        A[(ar+64)*KW  + ((wa+0) ^ sw1)] = packh2(a1v.x, a1v.y);
        A[(ar+64)*KW  + ((wa+1) ^ sw1)] = packh2(a1v.z, a1v.w);
        #pragma unroll
        for (int s = 0; s < 4; ++s)
            Bp[bn*KW + ((wb+s) ^ swb)] = packh2(br[2*s], br[2*s+1]);
    }
    __syncthreads();

    #pragma unroll 2
    for (int kt = 0; kt < NKT; ++kt) {
        // issue next tile's global loads early (hidden behind compute)
        if (kt + 1 < NKT) {
            int ko = (kt + 1) * BK;
            a0v = *(const float4*)(xp0 + ko);
            a1v = *(const float4*)(xp1 + ko);
            #pragma unroll
            for (int s = 0; s < 8; ++s) br[s] = wp[(size_t)(ko + s) * DD];
        }

        // compute from buf kt&1 : one m16n8k16 sweep covers BK=16
        {
            const unsigned* A  = As[kt & 1];
            const unsigned* Bp = Bs[kt & 1];
            const int t = lane & 3;
            const int g = lane >> 2;
            unsigned a[2][4], b[8][2];
            #pragma unroll
            for (int mt = 0; mt < 2; ++mt) {
                int r  = rB + mt * 16 + g;        // r&7 == g
                a[mt][0] = A[r*KW      + (t ^ g)];
                a[mt][1] = A[(r+8)*KW  + (t ^ g)];
                a[mt][2] = A[r*KW      + ((t+4) ^ g)];
                a[mt][3] = A[(r+8)*KW  + ((t+4) ^ g)];
            }
            #pragma unroll
            for (int nt = 0; nt < 8; ++nt) {
                int col = nB + nt * 8 + g;        // col&7 == g
                b[nt][0] = Bp[col*KW + (t ^ g)];
                b[nt][1] = Bp[col*KW + ((t+4) ^ g)];
            }
            #pragma unroll
            for (int mt = 0; mt < 2; ++mt)
                #pragma unroll
                for (int nt = 0; nt < 8; ++nt)
                    asm volatile(
                        "mma.sync.aligned.m16n8k16.row.col.f32.f16.f16.f32 "
                        "{%0,%1,%2,%3}, {%4,%5,%6,%7}, {%8,%9}, {%0,%1,%2,%3};"
                        : "+f"(c[mt][nt][0]), "+f"(c[mt][nt][1]),
                          "+f"(c[mt][nt][2]), "+f"(c[mt][nt][3])
                        : "r"(a[mt][0]), "r"(a[mt][1]), "r"(a[mt][2]), "r"(a[mt][3]),
                          "r"(b[nt][0]), "r"(b[nt][1]));
        }

        // store next tile into the other buffer (readers done at last sync)
        if (kt + 1 < NKT) {
            unsigned* A = As[(kt+1) & 1]; unsigned* Bp = Bs[(kt+1) & 1];
            A[ar*KW       + ((wa+0) ^ sw0)] = packh2(a0v.x, a0v.y);
            A[ar*KW       + ((wa+1) ^ sw0)] = packh2(a0v.z, a0v.w);
            A[(ar+64)*KW  + ((wa+0) ^ sw1)] = packh2(a1v.x, a1v.y);
            A[(ar+64)*KW  + ((wa+1) ^ sw1)] = packh2(a1v.z, a1v.w);
            #pragma unroll
            for (int s = 0; s < 4; ++s)
                Bp[bn*KW + ((wb+s) ^ swb)] = packh2(br[2*s], br[2*s+1]);
        }
        __syncthreads();
    }

    // Epilogue -> bf16 (c fragment layout identical to tf32 path)
    #pragma unroll
    for (int mt = 0; mt < 2; ++mt) {
        int r0 = m0 + rB + mt * 16 + (lane >> 2);
        #pragma unroll
        for (int nt = 0; nt < 8; ++nt) {
            int cc = n0 + nB + nt * 8 + (lane & 3) * 2;
            if (r0 < ROWS) {
                __nv_bfloat162 h = __float22bfloat162_rn(
                    make_float2(c[mt][nt][0], c[mt][nt][1]));
                *(__nv_bfloat162*)&Y[(size_t)r0 * DD + cc] = h;
            }
            if (r0 + 8 < ROWS) {
                __nv_bfloat162 h = __float22bfloat162_rn(
                    make_float2(c[mt][nt][2], c[mt][nt][3]));
                *(__nv_bfloat162*)&Y[(size_t)(r0 + 8) * DD + cc] = h;
            }
        }
    }
}

// ---------------------------------------------------------------------------
// Edge kernel: 4 edges per warp, batch = blockIdx.y. All 8 mask loads then
// all 8 row-gather LDG.128s issued before any compute -> MLP ~8 (was 2).
// Per-head dot (4 lanes x 8 dims), 2 xor shfls; quad leaders exp/store/atomic.
// Global-max shift is algebraically redundant in e/(seg+eps).
// ---------------------------------------------------------------------------
__global__ __launch_bounds__(256) void edge_kernel(const void* __restrict__ mask,
                                                   float* __restrict__ out)
{
    const int is64 = g_is64;
    const int b    = blockIdx.y;
    const int e0   = (int)((blockIdx.x * 8u + (threadIdx.x >> 5)) * 4u);
    const int lane = threadIdx.x & 31;

    int iv[4], jv[4];
    #pragma unroll
    for (int u = 0; u < 4; ++u) {
        iv[u] = mask_at(mask, 0, e0 + u, is64);
        jv[u] = mask_at(mask, 1, e0 + u, is64);
    }

    uint4 qv[4], kv[4];
    #pragma unroll
    for (int u = 0; u < 4; ++u) {
        qv[u] = ((const uint4*)(g_qh + (unsigned)(b * NN + iv[u]) * DD))[lane];
        kv[u] = ((const uint4*)(g_kh + (unsigned)(b * NN + jv[u]) * DD))[lane];
    }

    float s[4];
    #pragma unroll
    for (int u = 0; u < 4; ++u) {
        const __nv_bfloat162* qp = (const __nv_bfloat162*)&qv[u];
        const __nv_bfloat162* kp = (const __nv_bfloat162*)&kv[u];
        float acc = 0.0f;
        #pragma unroll
        for (int p = 0; p < 4; ++p) {
            float2 fa = __bfloat1622float2(qp[p]);
            float2 fb = __bfloat1622float2(kp[p]);
            acc += fa.x * fb.x + fa.y * fb.y;
        }
        acc += __shfl_xor_sync(0xffffffffu, acc, 1);
        acc += __shfl_xor_sync(0xffffffffu, acc, 2);
        s[u] = acc;                        // quad 4h..4h+3 hold head-h sum
    }

    if ((lane & 3) == 0) {
        const int h = lane >> 2;
        #pragma unroll
        for (int u = 0; u < 4; ++u) {
            float v = __expf(s[u] * 0.0625f);   // /sqrt(256)
            out[(unsigned)(b * MM + e0 + u) * HH + h] = v;
            atomicAdd(&g_seg[(unsigned)(b * NN + iv[u]) * HH + h], v);
        }
    }
}

// ---------------------------------------------------------------------------
// inv: one rcp per (b, node, h)
// ---------------------------------------------------------------------------
__global__ void inv_kernel() {
    int idx = blockIdx.x * blockDim.x + threadIdx.x;
    if (idx < BB*NN*HH) g_inv[idx] = 1.0f / (g_seg[idx] + 1e-16f);
}

// ---------------------------------------------------------------------------
// Normalize: thread per edge, batch = blockIdx.y; float4 x2 multiply.
// ---------------------------------------------------------------------------
__global__ __launch_bounds__(256) void norm_kernel(const void* __restrict__ mask,
                                                   float* __restrict__ out)
{
    const int is64 = g_is64;
    const int b = blockIdx.y;
    const int e = (int)(blockIdx.x * 256u + threadIdx.x);
    const int i = mask_at(mask, 0, e, is64);

    const float4* iv = (const float4*)(g_inv + (unsigned)(b * NN + i) * HH);
    float4 s0 = iv[0], s1 = iv[1];
    float4* op = (float4*)(out + (unsigned)(b * MM + e) * HH);
    float4 o0 = op[0], o1 = op[1];
    o0.x *= s0.x; o0.y *= s0.y; o0.z *= s0.z; o0.w *= s0.w;
    o1.x *= s1.x; o1.y *= s1.y; o1.z *= s1.z; o1.w *= s1.w;
    op[0] = o0; op[1] = o1;
}

// ---------------------------------------------------------------------------
extern "C" void kernel_launch(void* const* d_in, const int* in_sizes, int n_in,
                              void* d_out, int out_size)
{
    const float* x_q  = (const float*)d_in[0];
    const float* x_k  = (const float*)d_in[1];
    const void*  mask = d_in[2];
    const float* w_q  = (const float*)d_in[3];
    const float* w_k  = (const float*)d_in[4];
    float* out = (float*)d_out;

    detect_kernel<<<1, 32>>>((const unsigned*)mask);
    zero_seg_kernel<<<(BB*NN*HH + 255) / 256, 256>>>();

    dim3 gg((ROWS + BM - 1) / BM, DD / BN, 2);
    gemm_kernel<<<gg, 256>>>(x_q, x_k, w_q, w_k);

    dim3 ge(MM / 32, BB);           // 8 warps/block x 4 edges/warp, exact cover
    edge_kernel<<<ge, 256>>>(mask, out);

    inv_kernel<<<(BB*NN*HH + 255) / 256, 256>>>();

    dim3 gn(MM / 256, BB);          // exact cover
    norm_kernel<<<gn, 256>>>(mask, out);
}